// round 2
// baseline (speedup 1.0000x reference)
#include <cuda_runtime.h>
#include <stdint.h>

#define B_ 16
#define L_ 576
#define H_ 12
#define D_ 64
#define M_ 8
#define JT 32
#define RATIO 0.35355339059327373f   // 1/sqrt(8)
#define EPS 1e-3f

#define FMA2(acc, a, b) asm("fma.rn.f32x2 %0, %1, %2, %0;" : "+l"(acc) : "l"(a), "l"(b))
#define MUL2(d, a, b)   asm("mul.rn.f32x2 %0, %1, %2;"     : "=l"(d)   : "l"(a), "l"(b))
#define UNPK(lo, hi, x) asm("mov.b64 {%0, %1}, %2;" : "=f"(lo), "=f"(hi) : "l"(x))

// Scratch (device globals; no dynamic allocation allowed)
__device__ float g_qp[B_*H_*L_*M_];   // q' in [B,H,L,M]
__device__ float g_kp[B_*H_*L_*M_];   // k' in [B,H,L,M]
__device__ float g_s [H_*L_];         // column sums of mask
__device__ float g_ks[B_*H_*M_];      // ks_sum

// ---------------------------------------------------------------------------
// Feature kernel: qp/kp = relu(ratio * x @ proj^T) + eps, written as [B,H,L,M]
// ---------------------------------------------------------------------------
__global__ __launch_bounds__(128) void feat_kernel(const float* __restrict__ q,
                                                   const float* __restrict__ kk,
                                                   const float* __restrict__ proj)
{
    __shared__ float pr[M_*D_];
    int tid = threadIdx.x;
    for (int i = tid; i < M_*D_; i += 128) pr[i] = proj[i];
    __syncthreads();

    int rid = blockIdx.x * 128 + tid;          // row over (b,l,h)
    if (rid >= B_*L_*H_) return;

    const float* src = (blockIdx.y == 0 ? q : kk) + (size_t)rid * D_;
    float*       dst = (blockIdx.y == 0 ? g_qp : g_kp);

    float o[M_];
#pragma unroll
    for (int m = 0; m < M_; m++) o[m] = 0.f;

#pragma unroll
    for (int i = 0; i < D_/4; i++) {
        float4 x4 = ((const float4*)src)[i];
#pragma unroll
        for (int m = 0; m < M_; m++) {
            o[m] += x4.x * pr[m*D_ + 4*i + 0]
                  + x4.y * pr[m*D_ + 4*i + 1]
                  + x4.z * pr[m*D_ + 4*i + 2]
                  + x4.w * pr[m*D_ + 4*i + 3];
        }
    }

    int b   = rid / (L_*H_);
    int rem = rid - b*(L_*H_);
    int l   = rem / H_;
    int h   = rem - l*H_;
    size_t orow = ((size_t)(b*H_ + h)*L_ + l) * M_;

    float4 r0, r1;
    r0.x = fmaxf(o[0]*RATIO, 0.f) + EPS;
    r0.y = fmaxf(o[1]*RATIO, 0.f) + EPS;
    r0.z = fmaxf(o[2]*RATIO, 0.f) + EPS;
    r0.w = fmaxf(o[3]*RATIO, 0.f) + EPS;
    r1.x = fmaxf(o[4]*RATIO, 0.f) + EPS;
    r1.y = fmaxf(o[5]*RATIO, 0.f) + EPS;
    r1.z = fmaxf(o[6]*RATIO, 0.f) + EPS;
    r1.w = fmaxf(o[7]*RATIO, 0.f) + EPS;
    ((float4*)(dst + orow))[0] = r0;
    ((float4*)(dst + orow))[1] = r1;
}

// ---------------------------------------------------------------------------
// Column sums of mask: s[h,j] = sum_i mask[h,i,j]
// grid (L/64, H), 256 threads: 64 j-lanes x 4 i-groups -> high MLP, parallel
// ---------------------------------------------------------------------------
__global__ __launch_bounds__(256) void colsum_kernel(const float* __restrict__ mask)
{
    int h  = blockIdx.y;
    int j0 = blockIdx.x * 64;
    int jx = threadIdx.x & 63;
    int ig = threadIdx.x >> 6;
    const float* p = mask + (size_t)h*L_*L_ + j0 + jx;
    float acc = 0.f;
    for (int i = ig; i < L_; i += 4) acc += p[(size_t)i*L_];
    __shared__ float red[4][64];
    red[ig][jx] = acc;
    __syncthreads();
    if (threadIdx.x < 64) {
        g_s[h*L_ + j0 + threadIdx.x] = red[0][threadIdx.x] + red[1][threadIdx.x]
                                     + red[2][threadIdx.x] + red[3][threadIdx.x];
    }
}

// ---------------------------------------------------------------------------
// ks_sum[b,h,m] = sum_j s[h,j] * kp[b,h,j,m]      (one block per (b,h))
// ---------------------------------------------------------------------------
__global__ __launch_bounds__(128) void kssum_kernel()
{
    int bh = blockIdx.x;
    int h  = bh % H_;
    const float* kpr = g_kp + (size_t)bh*L_*M_;
    const float* sr  = g_s + h*L_;

    float a[8];
#pragma unroll
    for (int m = 0; m < 8; m++) a[m] = 0.f;

    for (int j = threadIdx.x; j < L_; j += 128) {
        float sv = sr[j];
        float4 x = ((const float4*)(kpr + j*8))[0];
        float4 y = ((const float4*)(kpr + j*8))[1];
        a[0] += sv*x.x; a[1] += sv*x.y; a[2] += sv*x.z; a[3] += sv*x.w;
        a[4] += sv*y.x; a[5] += sv*y.y; a[6] += sv*y.z; a[7] += sv*y.w;
    }
#pragma unroll
    for (int off = 16; off > 0; off >>= 1) {
#pragma unroll
        for (int m = 0; m < 8; m++)
            a[m] += __shfl_down_sync(0xffffffffu, a[m], off);
    }
    __shared__ float red[4][8];
    int w = threadIdx.x >> 5, lane = threadIdx.x & 31;
    if (lane == 0) {
#pragma unroll
        for (int m = 0; m < 8; m++) red[w][m] = a[m];
    }
    __syncthreads();
    if (threadIdx.x < 8) {
        g_ks[bh*8 + threadIdx.x] = red[0][threadIdx.x] + red[1][threadIdx.x]
                                 + red[2][threadIdx.x] + red[3][threadIdx.x];
    }
}

// ---------------------------------------------------------------------------
// Main kernel. Per (b,h): I=64 rows per block, loop j in tiles of JT=32.
//   W phase : w[i,jj] = mask[h,i,j]*dot8(qp[i],kp[j]) (f32x2 dot, smem [jj][i])
//   Main    : acc(i-pair, d) += (w[i],w[i+1]) * (v[d],v[d])
//             w pairs via natural LDS.64; v duplicated at staging -> no movs.
// Thread layout: tx = t&7 covers d = k*8+tx (k=0..7); ty = t>>3 covers
// rows ty*8 .. ty*8+7 as 4 f32x2 pairs.
// ---------------------------------------------------------------------------
__global__ __launch_bounds__(64, 6) void attn_kernel(const float* __restrict__ v,
                                                     const float* __restrict__ mask,
                                                     float* __restrict__ out)
{
    const int i0 = blockIdx.x * 64;
    const int h  = blockIdx.y;
    const int b  = blockIdx.z;
    const int bh = b*H_ + h;
    const int t  = threadIdx.x;   // 0..63
    const int tx = t & 7;
    const int ty = t >> 3;
    const int jw   = t & 31;      // W-phase jj lane
    const int half = t >> 5;      // W-phase i-half

    __shared__ __align__(16) float qp_s[64*8];        // 2 KB
    __shared__ __align__(16) float v_s2[JT*64*2];     // 16 KB (duplicated)
    __shared__ __align__(16) float w_s [JT*66];       // 8.25 KB

    // qp tile for this block (row t)
    {
        const float4* src = (const float4*)(g_qp + ((size_t)bh*L_ + i0 + t)*8);
        ((float4*)qp_s)[t*2]     = src[0];
        ((float4*)qp_s)[t*2 + 1] = src[1];
    }

    unsigned long long acc[4][8];
#pragma unroll
    for (int p = 0; p < 4; p++)
#pragma unroll
        for (int k = 0; k < 8; k++) acc[p][k] = 0ull;

    const float* vb  = v + ((size_t)b*L_*H_ + h)*64;          // + j*H*64 + d
    const float* mb  = mask + (size_t)h*L_*L_ + (size_t)i0*L_;
    const float* kpb = g_kp + (size_t)bh*L_*8;

    for (int j0 = 0; j0 < L_; j0 += JT) {
        __syncthreads();   // previous main loop done before smem reuse

        // stage v tile duplicated: v_s2[(jj*64+d)*2 .. +1] = v, v
#pragma unroll
        for (int qq = 0; qq < 8; qq++) {
            int idx = qq*64 + t;          // 0..511 float4s
            int jj = idx >> 4, c = idx & 15;
            float4 x = *(const float4*)(vb + (size_t)(j0 + jj)*(H_*64) + c*4);
            float* d0 = v_s2 + (jj*64 + c*4)*2;
            *(float4*)(d0)     = make_float4(x.x, x.x, x.y, x.y);
            *(float4*)(d0 + 4) = make_float4(x.z, x.z, x.w, x.w);
        }

        // this thread's k' row packed as f32x2 (jj = jw)
        unsigned long long kp2[4];
        {
            const ulonglong2* kr = (const ulonglong2*)(kpb + (size_t)(j0 + jw)*8);
            ulonglong2 a0 = kr[0], a1 = kr[1];
            kp2[0] = a0.x; kp2[1] = a0.y; kp2[2] = a1.x; kp2[3] = a1.y;
        }

        // W phase: each thread covers (jj = jw, rows half*32 .. half*32+31)
#pragma unroll 4
        for (int ii = 0; ii < 32; ii++) {
            int kI = half*32 + ii;
            ulonglong2 qA = *(const ulonglong2*)(qp_s + kI*8);
            ulonglong2 qB = *(const ulonglong2*)(qp_s + kI*8 + 4);
            float mval = mb[(size_t)kI*L_ + j0 + jw];
            unsigned long long d2;
            MUL2(d2, qA.x, kp2[0]);
            FMA2(d2, qA.y, kp2[1]);
            FMA2(d2, qB.x, kp2[2]);
            FMA2(d2, qB.y, kp2[3]);
            float lo, hi; UNPK(lo, hi, d2);
            w_s[jw*66 + kI] = mval * (lo + hi);
        }
        __syncthreads();

        // main accumulation: 4 i-pairs x 8 d per thread, all packed f32x2
#pragma unroll 2
        for (int jj = 0; jj < JT; jj++) {
            unsigned long long w2[4];
#pragma unroll
            for (int p = 0; p < 4; p++)
                w2[p] = *(const unsigned long long*)(w_s + jj*66 + ty*8 + 2*p);
            unsigned long long v2[8];
#pragma unroll
            for (int k = 0; k < 8; k++)
                v2[k] = *(const unsigned long long*)(v_s2 + (jj*64 + k*8 + tx)*2);
#pragma unroll
            for (int p = 0; p < 4; p++)
#pragma unroll
                for (int k = 0; k < 8; k++)
                    FMA2(acc[p][k], w2[p], v2[k]);
        }
    }

    // epilogue: normalizer + store
    float ks[8];
    {
        float4 a  = ((const float4*)(g_ks + bh*8))[0];
        float4 bb = ((const float4*)(g_ks + bh*8))[1];
        ks[0]=a.x; ks[1]=a.y; ks[2]=a.z; ks[3]=a.w;
        ks[4]=bb.x; ks[5]=bb.y; ks[6]=bb.z; ks[7]=bb.w;
    }
#pragma unroll
    for (int p = 0; p < 4; p++) {
        int r0 = ty*8 + 2*p;
        int r1 = r0 + 1;
        float n0 = 0.f, n1 = 0.f;
#pragma unroll
        for (int m = 0; m < 8; m++) {
            n0 += qp_s[r0*8 + m] * ks[m];
            n1 += qp_s[r1*8 + m] * ks[m];
        }
        float inv0 = 1.0f / n0;
        float inv1 = 1.0f / n1;
        float* o0 = out + (((size_t)b*L_ + i0 + r0)*H_ + h)*64;
        float* o1 = out + (((size_t)b*L_ + i0 + r1)*H_ + h)*64;
#pragma unroll
        for (int k = 0; k < 8; k++) {
            float lo, hi; UNPK(lo, hi, acc[p][k]);
            o0[k*8 + tx] = lo * inv0;
            o1[k*8 + tx] = hi * inv1;
        }
    }
}

// ---------------------------------------------------------------------------
extern "C" void kernel_launch(void* const* d_in, const int* in_sizes, int n_in,
                              void* d_out, int out_size)
{
    const float* q    = (const float*)d_in[0];
    const float* k    = (const float*)d_in[1];
    const float* v    = (const float*)d_in[2];
    const float* proj = (const float*)d_in[3];
    const float* mask = (const float*)d_in[4];
    float* out = (float*)d_out;

    dim3 fg((B_*L_*H_ + 127)/128, 2);
    feat_kernel<<<fg, 128>>>(q, k, proj);
    colsum_kernel<<<dim3(L_/64, H_), 256>>>(mask);
    kssum_kernel<<<B_*H_, 128>>>();
    attn_kernel<<<dim3(L_/64, H_, B_), 64>>>(v, mask, out);
}

// round 3
// speedup vs baseline: 1.1499x; 1.1499x over previous
#include <cuda_runtime.h>
#include <stdint.h>

#define B_ 16
#define L_ 576
#define H_ 12
#define D_ 64
#define M_ 8
#define JT 32
#define WPAD 132
#define RATIO 0.35355339059327373f   // 1/sqrt(8)
#define EPS 1e-3f

#define FMA2(acc, a, b) asm("fma.rn.f32x2 %0, %1, %2, %0;" : "+l"(acc) : "l"(a), "l"(b))
#define MUL2(d, a, b)   asm("mul.rn.f32x2 %0, %1, %2;"     : "=l"(d)   : "l"(a), "l"(b))
#define UNPK(lo, hi, x) asm("mov.b64 {%0, %1}, %2;" : "=f"(lo), "=f"(hi) : "l"(x))

// Scratch (device globals; no dynamic allocation allowed)
__device__ float g_qp[B_*H_*L_*M_];   // q' in [B,H,L,M]
__device__ float g_kp[B_*H_*L_*M_];   // k' in [B,H,L,M]
__device__ float g_s [H_*L_];         // column sums of mask
__device__ float g_ks[B_*H_*M_];      // ks_sum

// ---------------------------------------------------------------------------
// Feature kernel: qp/kp = relu(ratio * x @ proj^T) + eps, written as [B,H,L,M]
// ---------------------------------------------------------------------------
__global__ __launch_bounds__(128) void feat_kernel(const float* __restrict__ q,
                                                   const float* __restrict__ kk,
                                                   const float* __restrict__ proj)
{
    __shared__ float pr[M_*D_];
    int tid = threadIdx.x;
    for (int i = tid; i < M_*D_; i += 128) pr[i] = proj[i];
    __syncthreads();

    int rid = blockIdx.x * 128 + tid;          // row over (b,l,h)
    if (rid >= B_*L_*H_) return;

    const float* src = (blockIdx.y == 0 ? q : kk) + (size_t)rid * D_;
    float*       dst = (blockIdx.y == 0 ? g_qp : g_kp);

    float o[M_];
#pragma unroll
    for (int m = 0; m < M_; m++) o[m] = 0.f;

#pragma unroll
    for (int i = 0; i < D_/4; i++) {
        float4 x4 = ((const float4*)src)[i];
#pragma unroll
        for (int m = 0; m < M_; m++) {
            o[m] += x4.x * pr[m*D_ + 4*i + 0]
                  + x4.y * pr[m*D_ + 4*i + 1]
                  + x4.z * pr[m*D_ + 4*i + 2]
                  + x4.w * pr[m*D_ + 4*i + 3];
        }
    }

    int b   = rid / (L_*H_);
    int rem = rid - b*(L_*H_);
    int l   = rem / H_;
    int h   = rem - l*H_;
    size_t orow = ((size_t)(b*H_ + h)*L_ + l) * M_;

    float4 r0, r1;
    r0.x = fmaxf(o[0]*RATIO, 0.f) + EPS;
    r0.y = fmaxf(o[1]*RATIO, 0.f) + EPS;
    r0.z = fmaxf(o[2]*RATIO, 0.f) + EPS;
    r0.w = fmaxf(o[3]*RATIO, 0.f) + EPS;
    r1.x = fmaxf(o[4]*RATIO, 0.f) + EPS;
    r1.y = fmaxf(o[5]*RATIO, 0.f) + EPS;
    r1.z = fmaxf(o[6]*RATIO, 0.f) + EPS;
    r1.w = fmaxf(o[7]*RATIO, 0.f) + EPS;
    ((float4*)(dst + orow))[0] = r0;
    ((float4*)(dst + orow))[1] = r1;
}

// ---------------------------------------------------------------------------
// Column sums of mask: s[h,j] = sum_i mask[h,i,j]
// ---------------------------------------------------------------------------
__global__ __launch_bounds__(256) void colsum_kernel(const float* __restrict__ mask)
{
    int h  = blockIdx.y;
    int j0 = blockIdx.x * 64;
    int jx = threadIdx.x & 63;
    int ig = threadIdx.x >> 6;
    const float* p = mask + (size_t)h*L_*L_ + j0 + jx;
    float acc = 0.f;
    for (int i = ig; i < L_; i += 4) acc += p[(size_t)i*L_];
    __shared__ float red[4][64];
    red[ig][jx] = acc;
    __syncthreads();
    if (threadIdx.x < 64) {
        g_s[h*L_ + j0 + threadIdx.x] = red[0][threadIdx.x] + red[1][threadIdx.x]
                                     + red[2][threadIdx.x] + red[3][threadIdx.x];
    }
}

// ---------------------------------------------------------------------------
// ks_sum[b,h,m] = sum_j s[h,j] * kp[b,h,j,m]      (one block per (b,h))
// ---------------------------------------------------------------------------
__global__ __launch_bounds__(128) void kssum_kernel()
{
    int bh = blockIdx.x;
    int h  = bh % H_;
    const float* kpr = g_kp + (size_t)bh*L_*M_;
    const float* sr  = g_s + h*L_;

    float a[8];
#pragma unroll
    for (int m = 0; m < 8; m++) a[m] = 0.f;

    for (int j = threadIdx.x; j < L_; j += 128) {
        float sv = sr[j];
        float4 x = ((const float4*)(kpr + j*8))[0];
        float4 y = ((const float4*)(kpr + j*8))[1];
        a[0] += sv*x.x; a[1] += sv*x.y; a[2] += sv*x.z; a[3] += sv*x.w;
        a[4] += sv*y.x; a[5] += sv*y.y; a[6] += sv*y.z; a[7] += sv*y.w;
    }
#pragma unroll
    for (int off = 16; off > 0; off >>= 1) {
#pragma unroll
        for (int m = 0; m < 8; m++)
            a[m] += __shfl_down_sync(0xffffffffu, a[m], off);
    }
    __shared__ float red[4][8];
    int w = threadIdx.x >> 5, lane = threadIdx.x & 31;
    if (lane == 0) {
#pragma unroll
        for (int m = 0; m < 8; m++) red[w][m] = a[m];
    }
    __syncthreads();
    if (threadIdx.x < 8) {
        g_ks[bh*8 + threadIdx.x] = red[0][threadIdx.x] + red[1][threadIdx.x]
                                 + red[2][threadIdx.x] + red[3][threadIdx.x];
    }
}

// ---------------------------------------------------------------------------
// Main kernel. Per (b,h): I=64 rows per block, loop j in tiles of JT=32.
//   W phase : w = mask*dot8(qp,kp), stored DUPLICATED: w2_s[j][2i]=w2_s[j][2i+1]
//             -> main loop reads natural (w,w) pairs via LDS.128, no movs.
//   Main    : acc[row][dpair] += (w,w) * (v[d],v[d+1]); 8 rows x 4 d-pairs.
// Inner loop: 6 LDS.128 + 32 FMA2 per jj, base+immediate addressing.
// Thread map: tx=t&7 -> d = tx*4..+3 and 32+tx*4..+3; ty=t>>3 -> rows
// ty*4..+3 and 32+ty*4..+3.
// ---------------------------------------------------------------------------
__global__ __launch_bounds__(64, 6) void attn_kernel(const float* __restrict__ v,
                                                     const float* __restrict__ mask,
                                                     float* __restrict__ out)
{
    const int i0 = blockIdx.x * 64;
    const int h  = blockIdx.y;
    const int b  = blockIdx.z;
    const int bh = b*H_ + h;
    const int t  = threadIdx.x;   // 0..63
    const int tx = t & 7;
    const int ty = t >> 3;
    const int jw   = t & 31;      // W-phase j lane
    const int half = t >> 5;      // W-phase i-half

    __shared__ __align__(16) float qp_s[64*8];        // 2 KB
    __shared__ __align__(16) float v_s [JT*64];       // 8 KB
    __shared__ __align__(16) float w_s [JT*WPAD];     // 16.5 KB, dup'd pairs

    // qp tile for this block (row t)
    {
        const float4* src = (const float4*)(g_qp + ((size_t)bh*L_ + i0 + t)*8);
        ((float4*)qp_s)[t*2]     = src[0];
        ((float4*)qp_s)[t*2 + 1] = src[1];
    }

    unsigned long long acc[8][4];
#pragma unroll
    for (int r = 0; r < 8; r++)
#pragma unroll
        for (int c = 0; c < 4; c++) acc[r][c] = 0ull;

    const float* vb  = v + ((size_t)b*L_*H_ + h)*64;          // + j*H*64 + d
    const float* mb  = mask + (size_t)h*L_*L_ + (size_t)i0*L_;
    const float* kpb = g_kp + (size_t)bh*L_*8;

    for (int j0 = 0; j0 < L_; j0 += JT) {
        __syncthreads();   // previous main loop done before smem reuse

        // stage v tile [jj][d]: 32 rows x 64 floats, coalesced
#pragma unroll
        for (int qq = 0; qq < 8; qq++) {
            int idx = qq*64 + t;          // 0..511 float4s
            int jj = idx >> 4, c = idx & 15;
            *(float4*)(v_s + jj*64 + c*4) =
                *(const float4*)(vb + (size_t)(j0 + jj)*(H_*64) + c*4);
        }

        // this thread's k' row packed as f32x2 (j = j0 + jw)
        unsigned long long kp2[4];
        {
            const ulonglong2* kr = (const ulonglong2*)(kpb + (size_t)(j0 + jw)*8);
            ulonglong2 a0 = kr[0], a1 = kr[1];
            kp2[0] = a0.x; kp2[1] = a0.y; kp2[2] = a1.x; kp2[3] = a1.y;
        }

        // W phase: thread covers (j = jw, rows half*32 .. half*32+31)
        {
            const float* ml = mb + j0 + jw + (size_t)(half*32)*L_;
            float* wrow = w_s + jw*WPAD + half*64;
#pragma unroll 4
            for (int ii = 0; ii < 32; ii++) {
                int kI = half*32 + ii;
                ulonglong2 qA = *(const ulonglong2*)(qp_s + kI*8);
                ulonglong2 qB = *(const ulonglong2*)(qp_s + kI*8 + 4);
                float mval = ml[(size_t)ii*L_];
                unsigned long long d2;
                MUL2(d2, qA.x, kp2[0]);
                FMA2(d2, qA.y, kp2[1]);
                FMA2(d2, qB.x, kp2[2]);
                FMA2(d2, qB.y, kp2[3]);
                float lo, hi; UNPK(lo, hi, d2);
                float wv = mval * (lo + hi);
                *(float2*)(wrow + 2*ii) = make_float2(wv, wv);
            }
        }
        __syncthreads();

        // main accumulation: 8 rows x 4 d-pairs per thread, all packed f32x2
        {
            const float* wp = w_s + ty*8;      // dup'd rows ty*4..; +64 for hi half
            const float* vp = v_s + tx*4;
#pragma unroll 4
            for (int jj = 0; jj < JT; jj++) {
                ulonglong2 wA = *(const ulonglong2*)(wp + jj*WPAD);       // rows ty*4+0,1
                ulonglong2 wB = *(const ulonglong2*)(wp + jj*WPAD + 4);   // rows ty*4+2,3
                ulonglong2 wC = *(const ulonglong2*)(wp + jj*WPAD + 64);  // rows 32+ty*4+0,1
                ulonglong2 wD = *(const ulonglong2*)(wp + jj*WPAD + 68);  // rows 32+ty*4+2,3
                ulonglong2 v0 = *(const ulonglong2*)(vp + jj*64);         // d tx*4..+3
                ulonglong2 v1 = *(const ulonglong2*)(vp + jj*64 + 32);    // d 32+tx*4..+3

                FMA2(acc[0][0], wA.x, v0.x); FMA2(acc[0][1], wA.x, v0.y);
                FMA2(acc[0][2], wA.x, v1.x); FMA2(acc[0][3], wA.x, v1.y);
                FMA2(acc[1][0], wA.y, v0.x); FMA2(acc[1][1], wA.y, v0.y);
                FMA2(acc[1][2], wA.y, v1.x); FMA2(acc[1][3], wA.y, v1.y);
                FMA2(acc[2][0], wB.x, v0.x); FMA2(acc[2][1], wB.x, v0.y);
                FMA2(acc[2][2], wB.x, v1.x); FMA2(acc[2][3], wB.x, v1.y);
                FMA2(acc[3][0], wB.y, v0.x); FMA2(acc[3][1], wB.y, v0.y);
                FMA2(acc[3][2], wB.y, v1.x); FMA2(acc[3][3], wB.y, v1.y);
                FMA2(acc[4][0], wC.x, v0.x); FMA2(acc[4][1], wC.x, v0.y);
                FMA2(acc[4][2], wC.x, v1.x); FMA2(acc[4][3], wC.x, v1.y);
                FMA2(acc[5][0], wC.y, v0.x); FMA2(acc[5][1], wC.y, v0.y);
                FMA2(acc[5][2], wC.y, v1.x); FMA2(acc[5][3], wC.y, v1.y);
                FMA2(acc[6][0], wD.x, v0.x); FMA2(acc[6][1], wD.x, v0.y);
                FMA2(acc[6][2], wD.x, v1.x); FMA2(acc[6][3], wD.x, v1.y);
                FMA2(acc[7][0], wD.y, v0.x); FMA2(acc[7][1], wD.y, v0.y);
                FMA2(acc[7][2], wD.y, v1.x); FMA2(acc[7][3], wD.y, v1.y);
            }
        }
    }

    // epilogue: normalizer + store
    float ks[8];
    {
        float4 a  = ((const float4*)(g_ks + bh*8))[0];
        float4 bb = ((const float4*)(g_ks + bh*8))[1];
        ks[0]=a.x; ks[1]=a.y; ks[2]=a.z; ks[3]=a.w;
        ks[4]=bb.x; ks[5]=bb.y; ks[6]=bb.z; ks[7]=bb.w;
    }
#pragma unroll
    for (int r = 0; r < 8; r++) {
        int row = (r < 4) ? (ty*4 + r) : (32 + ty*4 + r - 4);
        float n = 0.f;
#pragma unroll
        for (int m = 0; m < 8; m++) n += qp_s[row*8 + m] * ks[m];
        float inv = 1.0f / n;

        float o[8];
#pragma unroll
        for (int c = 0; c < 4; c++)
            UNPK(o[2*c], o[2*c+1], acc[r][c]);

        float* op = out + (((size_t)b*L_ + i0 + row)*H_ + h)*64;
        *(float4*)(op + tx*4)      = make_float4(o[0]*inv, o[1]*inv, o[2]*inv, o[3]*inv);
        *(float4*)(op + 32 + tx*4) = make_float4(o[4]*inv, o[5]*inv, o[6]*inv, o[7]*inv);
    }
}

// ---------------------------------------------------------------------------
extern "C" void kernel_launch(void* const* d_in, const int* in_sizes, int n_in,
                              void* d_out, int out_size)
{
    const float* q    = (const float*)d_in[0];
    const float* k    = (const float*)d_in[1];
    const float* v    = (const float*)d_in[2];
    const float* proj = (const float*)d_in[3];
    const float* mask = (const float*)d_in[4];
    float* out = (float*)d_out;

    dim3 fg((B_*L_*H_ + 127)/128, 2);
    feat_kernel<<<fg, 128>>>(q, k, proj);
    colsum_kernel<<<dim3(L_/64, H_), 256>>>(mask);
    kssum_kernel<<<B_*H_, 128>>>();
    attn_kernel<<<dim3(L_/64, H_, B_), 64>>>(v, mask, out);
}

// round 4
// speedup vs baseline: 1.2457x; 1.0833x over previous
#include <cuda_runtime.h>
#include <stdint.h>

#define B_ 16
#define L_ 576
#define H_ 12
#define D_ 64
#define M_ 8
#define JT 32
#define NTILE (L_/JT)
#define WPAD 132
#define RATIO 0.35355339059327373f   // 1/sqrt(8)
#define EPS 1e-3f

#define FMA2(acc, a, b) asm("fma.rn.f32x2 %0, %1, %2, %0;" : "+l"(acc) : "l"(a), "l"(b))
#define MUL2(d, a, b)   asm("mul.rn.f32x2 %0, %1, %2;"     : "=l"(d)   : "l"(a), "l"(b))
#define UNPK(lo, hi, x) asm("mov.b64 {%0, %1}, %2;" : "=f"(lo), "=f"(hi) : "l"(x))
#define CPA16(dst_s, src_g) \
    asm volatile("cp.async.cg.shared.global [%0], [%1], 16;" :: "r"(dst_s), "l"(src_g))
#define CPA_COMMIT() asm volatile("cp.async.commit_group;")
#define CPA_WAIT(n)  asm volatile("cp.async.wait_group %0;" :: "n"(n))

// Scratch (device globals; no dynamic allocation allowed)
__device__ float g_qp[B_*H_*L_*M_];   // q' in [B,H,L,M]
__device__ float g_kp[B_*H_*L_*M_];   // k' in [B,H,L,M]
__device__ float g_s [H_*L_];         // column sums of mask
__device__ float g_ks[B_*H_*M_];      // ks_sum

// ---------------------------------------------------------------------------
// Feature kernel: qp/kp = relu(ratio * x @ proj^T) + eps, written as [B,H,L,M]
// ---------------------------------------------------------------------------
__global__ __launch_bounds__(128) void feat_kernel(const float* __restrict__ q,
                                                   const float* __restrict__ kk,
                                                   const float* __restrict__ proj)
{
    __shared__ float pr[M_*D_];
    int tid = threadIdx.x;
    for (int i = tid; i < M_*D_; i += 128) pr[i] = proj[i];
    __syncthreads();

    int rid = blockIdx.x * 128 + tid;          // row over (b,l,h)
    if (rid >= B_*L_*H_) return;

    const float* src = (blockIdx.y == 0 ? q : kk) + (size_t)rid * D_;
    float*       dst = (blockIdx.y == 0 ? g_qp : g_kp);

    float o[M_];
#pragma unroll
    for (int m = 0; m < M_; m++) o[m] = 0.f;

#pragma unroll
    for (int i = 0; i < D_/4; i++) {
        float4 x4 = ((const float4*)src)[i];
#pragma unroll
        for (int m = 0; m < M_; m++) {
            o[m] += x4.x * pr[m*D_ + 4*i + 0]
                  + x4.y * pr[m*D_ + 4*i + 1]
                  + x4.z * pr[m*D_ + 4*i + 2]
                  + x4.w * pr[m*D_ + 4*i + 3];
        }
    }

    int b   = rid / (L_*H_);
    int rem = rid - b*(L_*H_);
    int l   = rem / H_;
    int h   = rem - l*H_;
    size_t orow = ((size_t)(b*H_ + h)*L_ + l) * M_;

    float4 r0, r1;
    r0.x = fmaxf(o[0]*RATIO, 0.f) + EPS;
    r0.y = fmaxf(o[1]*RATIO, 0.f) + EPS;
    r0.z = fmaxf(o[2]*RATIO, 0.f) + EPS;
    r0.w = fmaxf(o[3]*RATIO, 0.f) + EPS;
    r1.x = fmaxf(o[4]*RATIO, 0.f) + EPS;
    r1.y = fmaxf(o[5]*RATIO, 0.f) + EPS;
    r1.z = fmaxf(o[6]*RATIO, 0.f) + EPS;
    r1.w = fmaxf(o[7]*RATIO, 0.f) + EPS;
    ((float4*)(dst + orow))[0] = r0;
    ((float4*)(dst + orow))[1] = r1;
}

// ---------------------------------------------------------------------------
// Column sums of mask: s[h,j] = sum_i mask[h,i,j]
// ---------------------------------------------------------------------------
__global__ __launch_bounds__(256) void colsum_kernel(const float* __restrict__ mask)
{
    int h  = blockIdx.y;
    int j0 = blockIdx.x * 64;
    int jx = threadIdx.x & 63;
    int ig = threadIdx.x >> 6;
    const float* p = mask + (size_t)h*L_*L_ + j0 + jx;
    float acc = 0.f;
    for (int i = ig; i < L_; i += 4) acc += p[(size_t)i*L_];
    __shared__ float red[4][64];
    red[ig][jx] = acc;
    __syncthreads();
    if (threadIdx.x < 64) {
        g_s[h*L_ + j0 + threadIdx.x] = red[0][threadIdx.x] + red[1][threadIdx.x]
                                     + red[2][threadIdx.x] + red[3][threadIdx.x];
    }
}

// ---------------------------------------------------------------------------
// ks_sum[b,h,m] = sum_j s[h,j] * kp[b,h,j,m]      (one block per (b,h))
// ---------------------------------------------------------------------------
__global__ __launch_bounds__(128) void kssum_kernel()
{
    int bh = blockIdx.x;
    int h  = bh % H_;
    const float* kpr = g_kp + (size_t)bh*L_*M_;
    const float* sr  = g_s + h*L_;

    float a[8];
#pragma unroll
    for (int m = 0; m < 8; m++) a[m] = 0.f;

    for (int j = threadIdx.x; j < L_; j += 128) {
        float sv = sr[j];
        float4 x = ((const float4*)(kpr + j*8))[0];
        float4 y = ((const float4*)(kpr + j*8))[1];
        a[0] += sv*x.x; a[1] += sv*x.y; a[2] += sv*x.z; a[3] += sv*x.w;
        a[4] += sv*y.x; a[5] += sv*y.y; a[6] += sv*y.z; a[7] += sv*y.w;
    }
#pragma unroll
    for (int off = 16; off > 0; off >>= 1) {
#pragma unroll
        for (int m = 0; m < 8; m++)
            a[m] += __shfl_down_sync(0xffffffffu, a[m], off);
    }
    __shared__ float red[4][8];
    int w = threadIdx.x >> 5, lane = threadIdx.x & 31;
    if (lane == 0) {
#pragma unroll
        for (int m = 0; m < 8; m++) red[w][m] = a[m];
    }
    __syncthreads();
    if (threadIdx.x < 8) {
        g_ks[bh*8 + threadIdx.x] = red[0][threadIdx.x] + red[1][threadIdx.x]
                                 + red[2][threadIdx.x] + red[3][threadIdx.x];
    }
}

// ---------------------------------------------------------------------------
// Main kernel, software-pipelined:
//   - mask tiles double-buffered in smem via cp.async (issued 1 tile ahead)
//   - v tile single-buffered via cp.async (issued at iter top, waited before
//     main loop -> latency covered by W phase)
//   - kp prefetched 1 tile ahead into registers
//   W phase : w = mask*dot8(qp,kp), stored duplicated (w,w) pairs
//   Main    : acc[row][dpair] += (w,w)*(v[d],v[d+1]); 8 rows x 4 d-pairs, FMA2
// ---------------------------------------------------------------------------
__global__ __launch_bounds__(64, 4) void attn_kernel(const float* __restrict__ v,
                                                     const float* __restrict__ mask,
                                                     float* __restrict__ out)
{
    const int i0 = blockIdx.x * 64;
    const int h  = blockIdx.y;
    const int b  = blockIdx.z;
    const int bh = b*H_ + h;
    const int t  = threadIdx.x;   // 0..63
    const int tx = t & 7;
    const int ty = t >> 3;
    const int jw   = t & 31;      // W-phase j lane
    const int half = t >> 5;      // W-phase i-half

    __shared__ __align__(16) float qp_s[64*8];        // 2 KB
    __shared__ __align__(16) float v_s [JT*64];       // 8 KB
    __shared__ __align__(16) float m_s [2][64*JT];    // 16 KB (double buffered)
    __shared__ __align__(16) float w_s [JT*WPAD];     // 16.5 KB, dup'd pairs

    // qp tile for this block (row t)
    {
        const float4* src = (const float4*)(g_qp + ((size_t)bh*L_ + i0 + t)*8);
        ((float4*)qp_s)[t*2]     = src[0];
        ((float4*)qp_s)[t*2 + 1] = src[1];
    }

    unsigned long long acc[8][4];
#pragma unroll
    for (int r = 0; r < 8; r++)
#pragma unroll
        for (int c = 0; c < 4; c++) acc[r][c] = 0ull;

    const float* vb  = v + ((size_t)b*L_*H_ + h)*64;          // + j*H*64 + d
    const float* mb  = mask + (size_t)h*L_*L_ + (size_t)i0*L_;
    const float* kpb = g_kp + (size_t)bh*L_*8;

    // mask staging indices: row = idx>>3 (0..63), col4 = idx&7
    const int mrow = t >> 3;            // rows covered: mrow, mrow+8, ... (qq*8)
    const int mcol = (t & 7) * 4;

    // ---- prologue: mask tile 0 -> buf 0; kp tile 0 -> regs
    {
        unsigned db = (unsigned)__cvta_generic_to_shared(m_s[0]);
#pragma unroll
        for (int qq = 0; qq < 8; qq++) {
            int row = qq*8 + mrow;
            CPA16(db + (unsigned)(row*JT + mcol)*4u, mb + (size_t)row*L_ + mcol);
        }
        CPA_COMMIT();
    }
    unsigned long long kpn[4];
    {
        const ulonglong2* kr = (const ulonglong2*)(kpb + (size_t)jw*8);
        ulonglong2 a0 = kr[0], a1 = kr[1];
        kpn[0] = a0.x; kpn[1] = a0.y; kpn[2] = a1.x; kpn[3] = a1.y;
    }
    CPA_WAIT(0);
    __syncthreads();

    for (int n = 0; n < NTILE; n++) {
        const int j0 = n * JT;
        const int j1 = (j0 + JT) % L_;       // next tile (wraps harmlessly)

        // current kp from prefetch; start prefetching next
        unsigned long long kpc[4];
#pragma unroll
        for (int p = 0; p < 4; p++) kpc[p] = kpn[p];
        {
            const ulonglong2* kr = (const ulonglong2*)(kpb + (size_t)(j1 + jw)*8);
            ulonglong2 a0 = kr[0], a1 = kr[1];
            kpn[0] = a0.x; kpn[1] = a0.y; kpn[2] = a1.x; kpn[3] = a1.y;
        }

        // issue v[n] (group), then mask[n+1] (group)
        {
            unsigned vdb = (unsigned)__cvta_generic_to_shared(v_s);
#pragma unroll
            for (int qq = 0; qq < 8; qq++) {
                int idx = qq*64 + t;
                int jj = idx >> 4, c = (idx & 15) * 4;
                CPA16(vdb + (unsigned)(jj*64 + c)*4u,
                      vb + (size_t)(j0 + jj)*(H_*64) + c);
            }
            CPA_COMMIT();
            unsigned mdb = (unsigned)__cvta_generic_to_shared(m_s[(n+1)&1]);
#pragma unroll
            for (int qq = 0; qq < 8; qq++) {
                int row = qq*8 + mrow;
                CPA16(mdb + (unsigned)(row*JT + mcol)*4u,
                      mb + (size_t)row*L_ + j1 + mcol);
            }
            CPA_COMMIT();
        }

        // W phase: thread covers (j = jw, rows half*32 .. half*32+31)
        {
            const float* mcur = m_s[n&1] + half*32*JT + jw;
            float* wrow = w_s + jw*WPAD + half*64;
#pragma unroll 4
            for (int ii = 0; ii < 32; ii++) {
                int kI = half*32 + ii;
                ulonglong2 qA = *(const ulonglong2*)(qp_s + kI*8);
                ulonglong2 qB = *(const ulonglong2*)(qp_s + kI*8 + 4);
                float mval = mcur[ii*JT];
                unsigned long long d2;
                MUL2(d2, qA.x, kpc[0]);
                FMA2(d2, qA.y, kpc[1]);
                FMA2(d2, qB.x, kpc[2]);
                FMA2(d2, qB.y, kpc[3]);
                float lo, hi; UNPK(lo, hi, d2);
                float wv = mval * (lo + hi);
                *(float2*)(wrow + 2*ii) = make_float2(wv, wv);
            }
        }
        CPA_WAIT(1);        // v[n] landed (mask[n+1] may still be in flight)
        __syncthreads();

        // main accumulation: 8 rows x 4 d-pairs per thread, all packed f32x2
        {
            const float* wp = w_s + ty*8;
            const float* vp = v_s + tx*4;
#pragma unroll 4
            for (int jj = 0; jj < JT; jj++) {
                ulonglong2 wA = *(const ulonglong2*)(wp + jj*WPAD);
                ulonglong2 wB = *(const ulonglong2*)(wp + jj*WPAD + 4);
                ulonglong2 wC = *(const ulonglong2*)(wp + jj*WPAD + 64);
                ulonglong2 wD = *(const ulonglong2*)(wp + jj*WPAD + 68);
                ulonglong2 v0 = *(const ulonglong2*)(vp + jj*64);
                ulonglong2 v1 = *(const ulonglong2*)(vp + jj*64 + 32);

                FMA2(acc[0][0], wA.x, v0.x); FMA2(acc[0][1], wA.x, v0.y);
                FMA2(acc[0][2], wA.x, v1.x); FMA2(acc[0][3], wA.x, v1.y);
                FMA2(acc[1][0], wA.y, v0.x); FMA2(acc[1][1], wA.y, v0.y);
                FMA2(acc[1][2], wA.y, v1.x); FMA2(acc[1][3], wA.y, v1.y);
                FMA2(acc[2][0], wB.x, v0.x); FMA2(acc[2][1], wB.x, v0.y);
                FMA2(acc[2][2], wB.x, v1.x); FMA2(acc[2][3], wB.x, v1.y);
                FMA2(acc[3][0], wB.y, v0.x); FMA2(acc[3][1], wB.y, v0.y);
                FMA2(acc[3][2], wB.y, v1.x); FMA2(acc[3][3], wB.y, v1.y);
                FMA2(acc[4][0], wC.x, v0.x); FMA2(acc[4][1], wC.x, v0.y);
                FMA2(acc[4][2], wC.x, v1.x); FMA2(acc[4][3], wC.x, v1.y);
                FMA2(acc[5][0], wC.y, v0.x); FMA2(acc[5][1], wC.y, v0.y);
                FMA2(acc[5][2], wC.y, v1.x); FMA2(acc[5][3], wC.y, v1.y);
                FMA2(acc[6][0], wD.x, v0.x); FMA2(acc[6][1], wD.x, v0.y);
                FMA2(acc[6][2], wD.x, v1.x); FMA2(acc[6][3], wD.x, v1.y);
                FMA2(acc[7][0], wD.y, v0.x); FMA2(acc[7][1], wD.y, v0.y);
                FMA2(acc[7][2], wD.y, v1.x); FMA2(acc[7][3], wD.y, v1.y);
            }
        }
        CPA_WAIT(0);        // mask[n+1] landed before anyone reads it
        __syncthreads();
    }

    // epilogue: normalizer + store
    float ks[8];
    {
        float4 a  = ((const float4*)(g_ks + bh*8))[0];
        float4 bb = ((const float4*)(g_ks + bh*8))[1];
        ks[0]=a.x; ks[1]=a.y; ks[2]=a.z; ks[3]=a.w;
        ks[4]=bb.x; ks[5]=bb.y; ks[6]=bb.z; ks[7]=bb.w;
    }
#pragma unroll
    for (int r = 0; r < 8; r++) {
        int row = (r < 4) ? (ty*4 + r) : (32 + ty*4 + r - 4);
        float n = 0.f;
#pragma unroll
        for (int m = 0; m < 8; m++) n += qp_s[row*8 + m] * ks[m];
        float inv = 1.0f / n;

        float o[8];
#pragma unroll
        for (int c = 0; c < 4; c++)
            UNPK(o[2*c], o[2*c+1], acc[r][c]);

        float* op = out + (((size_t)b*L_ + i0 + row)*H_ + h)*64;
        *(float4*)(op + tx*4)      = make_float4(o[0]*inv, o[1]*inv, o[2]*inv, o[3]*inv);
        *(float4*)(op + 32 + tx*4) = make_float4(o[4]*inv, o[5]*inv, o[6]*inv, o[7]*inv);
    }
}

// ---------------------------------------------------------------------------
extern "C" void kernel_launch(void* const* d_in, const int* in_sizes, int n_in,
                              void* d_out, int out_size)
{
    const float* q    = (const float*)d_in[0];
    const float* k    = (const float*)d_in[1];
    const float* v    = (const float*)d_in[2];
    const float* proj = (const float*)d_in[3];
    const float* mask = (const float*)d_in[4];
    float* out = (float*)d_out;

    dim3 fg((B_*L_*H_ + 127)/128, 2);
    feat_kernel<<<fg, 128>>>(q, k, proj);
    colsum_kernel<<<dim3(L_/64, H_), 256>>>(mask);
    kssum_kernel<<<B_*H_, 128>>>();
    attn_kernel<<<dim3(L_/64, H_, B_), 64>>>(v, mask, out);
}